// round 1
// baseline (speedup 1.0000x reference)
#include <cuda_runtime.h>
#include <math.h>

// ---------------- model constants ----------------
#define BATCH 128
#define EMB   256
#define NTOK  394          // 197 (p2 resampled) + 197 (p1)
#define NP    196          // patches used per image per stream
#define M_PE  (BATCH*NP)   // 25088
#define M_TOK (BATCH*NTOK) // 50432
#define K1    768          // 16*16*3
#define K2    192          // 8*8*3
#define SLD   400          // padded row for attn scores (394 -> 400)
#define SBH   ((long)NTOK*SLD) // per (b,h) score stride = 157600

// ---------------- scratch (static device memory; no allocs) ----------------
__device__ float g_P1[M_PE*K1];
__device__ float g_P2[M_PE*K2];
__device__ float g_E1[M_PE*EMB];
__device__ float g_E2[M_PE*EMB];
__device__ float g_Z [M_TOK*EMB];
__device__ float g_H [M_TOK*EMB];
__device__ float g_Q [M_TOK*EMB];
__device__ float g_K [M_TOK*EMB];
__device__ float g_V [M_TOK*EMB];
__device__ float g_S [256*NTOK*SLD];   // 256 (b,h) batches
__device__ float g_O [M_TOK*EMB];
__device__ float g_P [M_TOK*EMB];
__device__ float g_Z2[M_TOK*EMB];

// ---------------- helpers ----------------
__device__ __forceinline__ float blockReduce(float v, float* sh, bool ismax) {
    int lane = threadIdx.x & 31, w = threadIdx.x >> 5;
    int nw = blockDim.x >> 5;
    #pragma unroll
    for (int o = 16; o; o >>= 1) {
        float t = __shfl_down_sync(0xffffffffu, v, o);
        v = ismax ? fmaxf(v, t) : v + t;
    }
    if (lane == 0) sh[w] = v;
    __syncthreads();
    if (w == 0) {
        v = (lane < nw) ? sh[lane] : (ismax ? -INFINITY : 0.f);
        #pragma unroll
        for (int o = 16; o; o >>= 1) {
            float t = __shfl_down_sync(0xffffffffu, v, o);
            v = ismax ? fmaxf(v, t) : v + t;
        }
        if (lane == 0) sh[0] = v;
    }
    __syncthreads();
    float r = sh[0];
    __syncthreads();
    return r;
}

// ---------------- patch extraction ----------------
__global__ void extract1_kernel(const float* __restrict__ x) {
    int id = blockIdx.x * 256 + threadIdx.x;
    if (id >= M_PE * K1) return;
    int col = id % K1, r = id / K1;
    int b = r / NP, pi = r % NP;
    int ph = pi / 14, pw = pi % 14;
    int c = col % 3, s = col / 3;
    int pc = s % 16, pr = s / 16;
    g_P1[id] = x[(b*3 + c)*50176 + (ph*16 + pr)*224 + (pw*16 + pc)];
}

__global__ void extract2_kernel(const float* __restrict__ x) {
    int id = blockIdx.x * 256 + threadIdx.x;
    if (id >= M_PE * K2) return;
    int col = id % K2, r = id / K2;
    int b = r / NP, j = r % NP;
    int q = 4*j + 3;              // only patches actually sampled by linspace
    int ph = q / 28, pw = q % 28;
    int c = col % 3, s = col / 3;
    int pc = s % 8, pr = s / 8;
    g_P2[id] = x[(b*3 + c)*50176 + (ph*8 + pr)*224 + (pw*8 + pc)];
}

// ---------------- generic tiled SGEMM: C = A * op(B) + bias ----------------
// A: [M,K] row-major (lda), B: [K,N] row-major (ldb) or [N,K] if TRANSB.
// Batched over blockIdx.z -> b = z>>1, h = z&1, offsets via strides.
#define BM 64
#define BN 64
#define BK 16

template <bool TRANSB>
__global__ void sgemm_kernel(const float* __restrict__ Ag, const float* __restrict__ Bg,
                             const float* __restrict__ bias, float* __restrict__ Cg,
                             int M, int N, int K, int lda, int ldb, int ldc,
                             long sAb, long sAh, long sBb, long sBh, long sCb, long sCh)
{
    __shared__ float As[BK][BM];
    __shared__ float Bs[BK][BN + 4];

    int z = blockIdx.z;
    int bb = z >> 1, hh = z & 1;
    const float* A = Ag + bb*sAb + hh*sAh;
    const float* B = Bg + bb*sBb + hh*sBh;
    float* C = Cg + bb*sCb + hh*sCh;

    int row0 = blockIdx.y * BM;
    int col0 = blockIdx.x * BN;
    int tx = threadIdx.x, ty = threadIdx.y;
    int tid = ty * 16 + tx;

    float acc[4][4];
    #pragma unroll
    for (int i = 0; i < 4; i++)
        #pragma unroll
        for (int j = 0; j < 4; j++) acc[i][j] = 0.f;

    for (int k0 = 0; k0 < K; k0 += BK) {
        // ---- load A tile (64 rows x 16 k), float4 along k ----
        {
            int m = tid >> 2;
            int kk4 = (tid & 3) * 4;
            int row = row0 + m;
            int kbase = k0 + kk4;
            float v[4];
            if (row < M && kbase + 3 < K) {
                float4 t = *reinterpret_cast<const float4*>(&A[row*lda + kbase]);
                v[0]=t.x; v[1]=t.y; v[2]=t.z; v[3]=t.w;
            } else {
                #pragma unroll
                for (int t = 0; t < 4; t++)
                    v[t] = (row < M && kbase + t < K) ? A[row*lda + kbase + t] : 0.f;
            }
            #pragma unroll
            for (int t = 0; t < 4; t++) As[kk4 + t][m] = v[t];
        }
        // ---- load B tile ----
        if (!TRANSB) {
            int kk = tid >> 4;
            int n4 = (tid & 15) * 4;
            int kb = k0 + kk;
            int col = col0 + n4;
            if (kb < K && col + 3 < N) {
                float4 t = *reinterpret_cast<const float4*>(&B[kb*ldb + col]);
                *reinterpret_cast<float4*>(&Bs[kk][n4]) = t;
            } else {
                #pragma unroll
                for (int t = 0; t < 4; t++)
                    Bs[kk][n4 + t] = (kb < K && col + t < N) ? B[kb*ldb + col + t] : 0.f;
            }
        } else {
            int n = tid >> 2;
            int kk4 = (tid & 3) * 4;
            int colr = col0 + n;          // row of B (N dim)
            int kbase = k0 + kk4;
            float v[4];
            if (colr < N && kbase + 3 < K) {
                float4 t = *reinterpret_cast<const float4*>(&B[colr*ldb + kbase]);
                v[0]=t.x; v[1]=t.y; v[2]=t.z; v[3]=t.w;
            } else {
                #pragma unroll
                for (int t = 0; t < 4; t++)
                    v[t] = (colr < N && kbase + t < K) ? B[colr*ldb + kbase + t] : 0.f;
            }
            #pragma unroll
            for (int t = 0; t < 4; t++) Bs[kk4 + t][n] = v[t];
        }
        __syncthreads();

        // ---- compute ----
        #pragma unroll
        for (int kk = 0; kk < BK; kk++) {
            float4 a = *reinterpret_cast<const float4*>(&As[kk][ty*4]);
            float4 b4 = *reinterpret_cast<const float4*>(&Bs[kk][tx*4]);
            float av[4] = {a.x, a.y, a.z, a.w};
            float bv[4] = {b4.x, b4.y, b4.z, b4.w};
            #pragma unroll
            for (int i = 0; i < 4; i++)
                #pragma unroll
                for (int j = 0; j < 4; j++)
                    acc[i][j] += av[i] * bv[j];
        }
        __syncthreads();
    }

    // ---- store ----
    #pragma unroll
    for (int i = 0; i < 4; i++) {
        int row = row0 + ty*4 + i;
        if (row >= M) continue;
        #pragma unroll
        for (int j = 0; j < 4; j++) {
            int col = col0 + tx*4 + j;
            if (col < N)
                C[row*ldc + col] = acc[i][j] + (bias ? bias[col] : 0.f);
        }
    }
}

// ---------------- z assembly ----------------
__global__ void buildZ_kernel(const float* __restrict__ cls1, const float* __restrict__ cls2) {
    int id = blockIdx.x * 256 + threadIdx.x;
    if (id >= M_TOK * EMB) return;
    int e = id % EMB;
    int t = (id / EMB) % NTOK;
    int b = id / (EMB * NTOK);
    float v;
    if (t == 0)        v = cls2[e];
    else if (t < 197)  v = g_E2[(b*NP + (t-1))*EMB + e];
    else if (t == 197) v = cls1[e];
    else               v = g_E1[(b*NP + (t-198))*EMB + e];
    g_Z[id] = v;
}

// ---------------- layernorm over last-dim 256 ----------------
__global__ void ln_kernel(const float* __restrict__ X, const float* __restrict__ g,
                          const float* __restrict__ b, float* __restrict__ Y) {
    __shared__ float sh[8];
    int t = blockIdx.x, e = threadIdx.x;
    float v = X[t*EMB + e];
    float m = blockReduce(v, sh, false) * (1.f/EMB);
    float d = v - m;
    float var = blockReduce(d*d, sh, false) * (1.f/EMB);
    Y[t*EMB + e] = d * rsqrtf(var + 1e-5f) * g[e] + b[e];
}

// residual: Z2 = Z + LN(P)
__global__ void lnres_kernel(const float* __restrict__ Pm, const float* __restrict__ g,
                             const float* __restrict__ b) {
    __shared__ float sh[8];
    int t = blockIdx.x, e = threadIdx.x;
    float v = Pm[t*EMB + e];
    float m = blockReduce(v, sh, false) * (1.f/EMB);
    float d = v - m;
    float var = blockReduce(d*d, sh, false) * (1.f/EMB);
    float o = d * rsqrtf(var + 1e-5f) * g[e] + b[e];
    g_Z2[t*EMB + e] = g_Z[t*EMB + e] + o;
}

// ---------------- softmax (then /16) per score row ----------------
__global__ void softmax_kernel() {
    __shared__ float sh[4];
    int bh = blockIdx.y;
    int q  = blockIdx.x;
    float* row = g_S + (long)bh * SBH + (long)q * SLD;
    int tid = threadIdx.x;

    float mx = -INFINITY;
    for (int i = tid; i < NTOK; i += 128) mx = fmaxf(mx, row[i]);
    mx = blockReduce(mx, sh, true);

    float s = 0.f;
    for (int i = tid; i < NTOK; i += 128) {
        float e = expf(row[i] - mx);
        row[i] = e;
        s += e;
    }
    s = blockReduce(s, sh, false);
    float inv = 1.f / (s * 16.f);   // softmax then divide by sqrt(256)
    for (int i = tid; i < NTOK; i += 128) row[i] *= inv;
}

// ---------------- classifier head ----------------
__global__ void head_kernel(const float* __restrict__ g, const float* __restrict__ b,
                            const float* __restrict__ Wc, const float* __restrict__ bc,
                            float* __restrict__ out) {
    __shared__ float sh[8];
    int bb = blockIdx.x, e = threadIdx.x;
    const float* p = g_Z2 + (long)bb * NTOK * EMB + e;
    float s = 0.f;
    for (int t = 0; t < NTOK; t++) s += p[t*EMB];
    float pooled = s * (1.f/NTOK);
    float m = blockReduce(pooled, sh, false) * (1.f/EMB);
    float d = pooled - m;
    float var = blockReduce(d*d, sh, false) * (1.f/EMB);
    float y = d * rsqrtf(var + 1e-5f) * g[e] + b[e];
    float p0 = blockReduce(y * Wc[e*2 + 0], sh, false);
    float p1 = blockReduce(y * Wc[e*2 + 1], sh, false);
    if (e == 0) {
        float l0 = p0 + bc[0], l1 = p1 + bc[1];
        float mm = fmaxf(l0, l1);
        float lse = mm + logf(expf(l0 - mm) + expf(l1 - mm));
        out[bb*2 + 0] = l0 - lse;
        out[bb*2 + 1] = l1 - lse;
    }
}

// ---------------- launch ----------------
extern "C" void kernel_launch(void* const* d_in, const int* in_sizes, int n_in,
                              void* d_out, int out_size)
{
    const float* x    = (const float*)d_in[0];
    const float* W1   = (const float*)d_in[1];
    const float* b1   = (const float*)d_in[2];
    const float* cls1 = (const float*)d_in[3];
    const float* W2   = (const float*)d_in[4];
    const float* b2   = (const float*)d_in[5];
    const float* cls2 = (const float*)d_in[6];
    const float* ln1g = (const float*)d_in[7];
    const float* ln1b = (const float*)d_in[8];
    const float* Wq   = (const float*)d_in[9];
    const float* bq   = (const float*)d_in[10];
    const float* Wk   = (const float*)d_in[11];
    const float* bk   = (const float*)d_in[12];
    const float* Wv   = (const float*)d_in[13];
    const float* bv   = (const float*)d_in[14];
    const float* Wp   = (const float*)d_in[15];
    const float* bp   = (const float*)d_in[16];
    const float* ln2g = (const float*)d_in[17];
    const float* ln2b = (const float*)d_in[18];
    const float* lncg = (const float*)d_in[19];
    const float* lncb = (const float*)d_in[20];
    const float* Wc   = (const float*)d_in[21];
    const float* bc   = (const float*)d_in[22];
    float* out = (float*)d_out;

    float *P1, *P2, *E1, *E2, *Z, *H, *Q, *Kb, *V, *S, *O, *P;
    cudaGetSymbolAddress((void**)&P1, g_P1);
    cudaGetSymbolAddress((void**)&P2, g_P2);
    cudaGetSymbolAddress((void**)&E1, g_E1);
    cudaGetSymbolAddress((void**)&E2, g_E2);
    cudaGetSymbolAddress((void**)&Z,  g_Z);
    cudaGetSymbolAddress((void**)&H,  g_H);
    cudaGetSymbolAddress((void**)&Q,  g_Q);
    cudaGetSymbolAddress((void**)&Kb, g_K);
    cudaGetSymbolAddress((void**)&V,  g_V);
    cudaGetSymbolAddress((void**)&S,  g_S);
    cudaGetSymbolAddress((void**)&O,  g_O);
    cudaGetSymbolAddress((void**)&P,  g_P);

    dim3 thr(16, 16);

    // patch extraction
    extract1_kernel<<<(M_PE*K1 + 255)/256, 256>>>(x);
    extract2_kernel<<<(M_PE*K2 + 255)/256, 256>>>(x);

    // patch embed GEMMs -> E1, E2
    sgemm_kernel<false><<<dim3(4, (M_PE+BM-1)/BM, 1), thr>>>(
        P1, W1, b1, E1, M_PE, EMB, K1, K1, EMB, EMB, 0,0,0,0,0,0);
    sgemm_kernel<false><<<dim3(4, (M_PE+BM-1)/BM, 1), thr>>>(
        P2, W2, b2, E2, M_PE, EMB, K2, K2, EMB, EMB, 0,0,0,0,0,0);

    // assemble z, layernorm -> H
    buildZ_kernel<<<(M_TOK*EMB + 255)/256, 256>>>(cls1, cls2);
    ln_kernel<<<M_TOK, 256>>>(Z, ln1g, ln1b, H);

    // Q, K, V
    sgemm_kernel<false><<<dim3(4, (M_TOK+BM-1)/BM, 1), thr>>>(
        H, Wq, bq, Q, M_TOK, EMB, EMB, EMB, EMB, EMB, 0,0,0,0,0,0);
    sgemm_kernel<false><<<dim3(4, (M_TOK+BM-1)/BM, 1), thr>>>(
        H, Wk, bk, Kb, M_TOK, EMB, EMB, EMB, EMB, EMB, 0,0,0,0,0,0);
    sgemm_kernel<false><<<dim3(4, (M_TOK+BM-1)/BM, 1), thr>>>(
        H, Wv, bv, V, M_TOK, EMB, EMB, EMB, EMB, EMB, 0,0,0,0,0,0);

    // S = Q @ K^T  (batched over 256 (b,h))
    {
        long sAb = (long)NTOK*EMB, sAh = 128;
        long sCb = 2*SBH, sCh = SBH;
        sgemm_kernel<true><<<dim3(7, 7, 256), thr>>>(
            Q, Kb, nullptr, S, NTOK, NTOK, 128, EMB, EMB, SLD,
            sAb, sAh, sAb, sAh, sCb, sCh);
    }

    // softmax / 16
    softmax_kernel<<<dim3(NTOK, 256), 128>>>();

    // O = S @ V  (batched)
    {
        long sAb = 2*SBH, sAh = SBH;
        long sBb = (long)NTOK*EMB, sBh = 128;
        sgemm_kernel<false><<<dim3(2, 7, 256), thr>>>(
            S, V, nullptr, O, NTOK, 128, NTOK, SLD, EMB, EMB,
            sAb, sAh, sBb, sBh, sBb, sBh);
    }

    // projection
    sgemm_kernel<false><<<dim3(4, (M_TOK+BM-1)/BM, 1), thr>>>(
        O, Wp, bp, P, M_TOK, EMB, EMB, EMB, EMB, EMB, 0,0,0,0,0,0);

    // Z2 = Z + LN(P)
    lnres_kernel<<<M_TOK, 256>>>(P, ln2g, ln2b);

    // pooled -> LN -> logits -> log_softmax
    head_kernel<<<BATCH, 256>>>(lncg, lncb, Wc, bc, out);
}

// round 4
// speedup vs baseline: 1.3805x; 1.3805x over previous
#include <cuda_runtime.h>
#include <cuda_bf16.h>
#include <cstdint>
#include <math.h>

#define BATCH 128
#define EMB   256
#define NTOK  394
#define NP    196
#define M_PE  (BATCH*NP)
#define M_TOK (BATCH*NTOK)
#define SLD   400
#define NT_PAD 448
#define AST   40   // smem row stride in bf16 (80B, conflict-free ldmatrix)

// ---------------- scratch ----------------
__device__ __nv_bfloat16 g_A1[(size_t)M_PE*2304];
__device__ __nv_bfloat16 g_A2[(size_t)M_PE*576];
__device__ __nv_bfloat16 g_W1T[256*2304];
__device__ __nv_bfloat16 g_W2T[256*576];
__device__ __nv_bfloat16 g_WqkvT[768*768];
__device__ __nv_bfloat16 g_WpT[256*768];
__device__ float g_bqkv[768];
__device__ float g_E1[(size_t)M_PE*EMB];
__device__ float g_E2[(size_t)M_PE*EMB];
__device__ float g_Z [(size_t)M_TOK*EMB];
__device__ __nv_bfloat16 g_Hs[(size_t)M_TOK*768];
__device__ float g_QKV[(size_t)M_TOK*768];
__device__ __nv_bfloat16 g_Qs[(size_t)256*NTOK*384];
__device__ __nv_bfloat16 g_Ks[(size_t)256*NTOK*384];
__device__ __nv_bfloat16 g_Vt[(size_t)256*128*1344];
__device__ float g_S [(size_t)256*NTOK*SLD];
__device__ __nv_bfloat16 g_Ps[(size_t)256*NTOK*1344];
__device__ float g_O [(size_t)M_TOK*EMB];
__device__ __nv_bfloat16 g_Os[(size_t)M_TOK*768];
__device__ float g_P [(size_t)M_TOK*EMB];
__device__ float g_Z2[(size_t)M_TOK*EMB];

__device__ __forceinline__ uint32_t smem_u32(const void* p) {
    uint32_t a;
    asm("{ .reg .u64 t; cvta.to.shared.u64 t, %1; cvt.u32.u64 %0, t; }" : "=r"(a) : "l"(p));
    return a;
}
__device__ __forceinline__ void ldm4(uint32_t* r, uint32_t addr) {
    asm volatile("ldmatrix.sync.aligned.m8n8.x4.shared.b16 {%0,%1,%2,%3}, [%4];"
        : "=r"(r[0]), "=r"(r[1]), "=r"(r[2]), "=r"(r[3]) : "r"(addr));
}
__device__ __forceinline__ void mma16816(float* c, const uint32_t* a, uint32_t b0, uint32_t b1) {
    asm volatile(
        "mma.sync.aligned.m16n8k16.row.col.f32.bf16.bf16.f32 "
        "{%0,%1,%2,%3}, {%4,%5,%6,%7}, {%8,%9}, {%0,%1,%2,%3};"
        : "+f"(c[0]), "+f"(c[1]), "+f"(c[2]), "+f"(c[3])
        : "r"(a[0]), "r"(a[1]), "r"(a[2]), "r"(a[3]), "r"(b0), "r"(b1));
}

// ============ warp-MMA GEMM: C[M,N] = A[M,K] @ B[N,K]^T (+bias) ============
// A, B bf16 K-major. K must be a multiple of 32. Batched over blockIdx.z.
__global__ void __launch_bounds__(256) gemm_mma(
    const __nv_bfloat16* __restrict__ Ag, const __nv_bfloat16* __restrict__ Bg,
    const float* __restrict__ bias, float* __restrict__ Cg,
    int M, int N, int K, int lda, int ldb, int ldc,
    long sAz2, long sAz1, long sBz2, long sBz1, long sCz2, long sCz1)
{
    __shared__ __align__(16) __nv_bfloat16 As[2][128*AST];
    __shared__ __align__(16) __nv_bfloat16 Bs[2][128*AST];

    int tid = threadIdx.x, wid = tid >> 5, lane = tid & 31;
    int z = blockIdx.z;
    const __nv_bfloat16* A = Ag + (long)(z >> 1) * sAz2 + (long)(z & 1) * sAz1;
    const __nv_bfloat16* B = Bg + (long)(z >> 1) * sBz2 + (long)(z & 1) * sBz1;
    float* C = Cg + (long)(z >> 1) * sCz2 + (long)(z & 1) * sCz1;
    int row0 = blockIdx.y * 128, col0 = blockIdx.x * 128;
    A += (size_t)row0 * lda;
    B += (size_t)col0 * ldb;
    C += (size_t)row0 * ldc + col0;
    int Mrem = M - row0, Nrem = N - col0;

    int wm = wid & 3, wn = wid >> 2;       // warp tile: 32 (M) x 64 (N)
    int ldrow = tid >> 1, ldhalf = tid & 1;
    bool aval = ldrow < Mrem, bval = ldrow < Nrem;
    const __nv_bfloat16* ga = A + (size_t)ldrow * lda + ldhalf * 16;
    const __nv_bfloat16* gb = B + (size_t)ldrow * ldb + ldhalf * 16;
    uint32_t sdstA = smem_u32(&As[0][0]) + (ldrow * AST + ldhalf * 16) * 2;
    uint32_t sdstB = smem_u32(&Bs[0][0]) + (ldrow * AST + ldhalf * 16) * 2;
    const uint32_t ABYTES = 128 * AST * 2;
    const uint4 z4 = make_uint4(0, 0, 0, 0);

    // ldmatrix source offsets
    uint32_t sAb = smem_u32(&As[0][0]);
    uint32_t sBb = smem_u32(&Bs[0][0]);
    uint32_t aoff = ((wm * 32 + (lane & 15)) * AST + ((lane >> 4) * 8)) * 2;
    uint32_t boff = ((wn * 64 + (lane & 7) + ((lane >> 4) & 1) * 8) * AST) * 2
                  + ((lane >> 3) & 1) * 16;

    float acc[2][8][4];
    #pragma unroll
    for (int i = 0; i < 2; i++)
        #pragma unroll
        for (int j = 0; j < 8; j++)
            #pragma unroll
            for (int t = 0; t < 4; t++) acc[i][j][t] = 0.f;

    int nchunk = K >> 5;
    // prologue: chunk 0 -> buf 0
    {
        uint4 va0 = aval ? *reinterpret_cast<const uint4*>(ga)     : z4;
        uint4 va1 = aval ? *reinterpret_cast<const uint4*>(ga + 8) : z4;
        uint4 vb0 = bval ? *reinterpret_cast<const uint4*>(gb)     : z4;
        uint4 vb1 = bval ? *reinterpret_cast<const uint4*>(gb + 8) : z4;
        *reinterpret_cast<uint4*>(reinterpret_cast<char*>(&As[0][0]) + (sdstA - sAb)) = va0;
        *reinterpret_cast<uint4*>(reinterpret_cast<char*>(&As[0][0]) + (sdstA - sAb) + 16) = va1;
        *reinterpret_cast<uint4*>(reinterpret_cast<char*>(&Bs[0][0]) + (sdstB - sBb)) = vb0;
        *reinterpret_cast<uint4*>(reinterpret_cast<char*>(&Bs[0][0]) + (sdstB - sBb) + 16) = vb1;
    }
    __syncthreads();

    for (int i = 0; i < nchunk; i++) {
        uint4 va0, va1, vb0, vb1;
        bool more = (i + 1) < nchunk;
        if (more) {
            const __nv_bfloat16* pa = ga + (size_t)(i + 1) * 32;
            const __nv_bfloat16* pb = gb + (size_t)(i + 1) * 32;
            va0 = aval ? *reinterpret_cast<const uint4*>(pa)     : z4;
            va1 = aval ? *reinterpret_cast<const uint4*>(pa + 8) : z4;
            vb0 = bval ? *reinterpret_cast<const uint4*>(pb)     : z4;
            vb1 = bval ? *reinterpret_cast<const uint4*>(pb + 8) : z4;
        }
        uint32_t sA = sAb + (i & 1) * ABYTES;
        uint32_t sB = sBb + (i & 1) * ABYTES;
        #pragma unroll
        for (int kk = 0; kk < 2; kk++) {
            uint32_t a0[4], a1[4], bf[4][4];
            ldm4(a0, sA + aoff + kk * 32);
            ldm4(a1, sA + aoff + 16 * AST * 2 + kk * 32);
            #pragma unroll
            for (int j = 0; j < 4; j++)
                ldm4(bf[j], sB + boff + j * 16 * AST * 2 + kk * 32);
            #pragma unroll
            for (int j = 0; j < 4; j++) {
                mma16816(acc[0][2*j],   a0, bf[j][0], bf[j][1]);
                mma16816(acc[0][2*j+1], a0, bf[j][2], bf[j][3]);
                mma16816(acc[1][2*j],   a1, bf[j][0], bf[j][1]);
                mma16816(acc[1][2*j+1], a1, bf[j][2], bf[j][3]);
            }
        }
        __syncthreads();
        if (more) {
            int nb = (i + 1) & 1;
            uint32_t dA = (sdstA - sAb) + nb * ABYTES;
            uint32_t dB = (sdstB - sBb) + nb * ABYTES;
            *reinterpret_cast<uint4*>(reinterpret_cast<char*>(&As[0][0]) + dA) = va0;
            *reinterpret_cast<uint4*>(reinterpret_cast<char*>(&As[0][0]) + dA + 16) = va1;
            *reinterpret_cast<uint4*>(reinterpret_cast<char*>(&Bs[0][0]) + dB) = vb0;
            *reinterpret_cast<uint4*>(reinterpret_cast<char*>(&Bs[0][0]) + dB + 16) = vb1;
            __syncthreads();
        }
    }

    // epilogue
    int grp = lane >> 2, qd = lane & 3;
    #pragma unroll
    for (int mt = 0; mt < 2; mt++) {
        int r0 = wm * 32 + mt * 16 + grp;
        #pragma unroll
        for (int nt = 0; nt < 8; nt++) {
            int c = wn * 64 + nt * 8 + qd * 2;
            float b0v = 0.f, b1v = 0.f;
            if (bias) { b0v = bias[col0 + c]; b1v = bias[col0 + c + 1]; }
            if (r0 < Mrem) {
                if (c < Nrem)     C[(size_t)r0 * ldc + c]     = acc[mt][nt][0] + b0v;
                if (c + 1 < Nrem) C[(size_t)r0 * ldc + c + 1] = acc[mt][nt][1] + b1v;
            }
            if (r0 + 8 < Mrem) {
                if (c < Nrem)     C[(size_t)(r0 + 8) * ldc + c]     = acc[mt][nt][2] + b0v;
                if (c + 1 < Nrem) C[(size_t)(r0 + 8) * ldc + c + 1] = acc[mt][nt][3] + b1v;
            }
        }
    }
}

// ================ conversion / pointwise kernels ================
__device__ __forceinline__ void split2(float v, __nv_bfloat16& hi, __nv_bfloat16& lo) {
    hi = __float2bfloat16(v);
    lo = __float2bfloat16(v - __bfloat162float(hi));
}

__global__ void convW_kernel(const float* __restrict__ W, __nv_bfloat16* __restrict__ out,
                             int K, int N, int nOff, int ldout) {
    int id = blockIdx.x * 256 + threadIdx.x;
    if (id >= K * N) return;
    int k = id / N, n = id % N;
    __nv_bfloat16 hi, lo; split2(W[(size_t)k * N + n], hi, lo);
    size_t base = (size_t)(nOff + n) * ldout;
    out[base + k] = hi; out[base + K + k] = hi; out[base + 2 * K + k] = lo;
}

__global__ void catBias_kernel(const float* a, const float* b, const float* c) {
    int i = blockIdx.x * 256 + threadIdx.x;
    if (i < 256) g_bqkv[i] = a[i];
    else if (i < 512) g_bqkv[i] = b[i - 256];
    else if (i < 768) g_bqkv[i] = c[i - 512];
}

__global__ void extract_split1(const float* __restrict__ x) {
    int id = blockIdx.x * 256 + threadIdx.x;
    if (id >= M_PE * 768) return;
    int col = id % 768, rw = id / 768;
    int b = rw / NP, pi = rw % NP;
    int ph = pi / 14, pw = pi % 14;
    int c = col % 3, s = col / 3;
    int pc = s % 16, pr = s / 16;
    float v = x[(size_t)(b * 3 + c) * 50176 + (ph * 16 + pr) * 224 + (pw * 16 + pc)];
    __nv_bfloat16 hi, lo; split2(v, hi, lo);
    size_t base = (size_t)rw * 2304;
    g_A1[base + col] = hi; g_A1[base + 768 + col] = lo; g_A1[base + 1536 + col] = hi;
}

__global__ void extract_split2(const float* __restrict__ x) {
    int id = blockIdx.x * 256 + threadIdx.x;
    if (id >= M_PE * 192) return;
    int col = id % 192, rw = id / 192;
    int b = rw / NP, j = rw % NP;
    int q = 4 * j + 3;
    int ph = q / 28, pw = q % 28;
    int c = col % 3, s = col / 3;
    int pc = s % 8, pr = s / 8;
    float v = x[(size_t)(b * 3 + c) * 50176 + (ph * 8 + pr) * 224 + (pw * 8 + pc)];
    __nv_bfloat16 hi, lo; split2(v, hi, lo);
    size_t base = (size_t)rw * 576;
    g_A2[base + col] = hi; g_A2[base + 192 + col] = lo; g_A2[base + 384 + col] = hi;
}

__device__ __forceinline__ float blockReduce(float v, float* sh, bool ismax) {
    int lane = threadIdx.x & 31, w = threadIdx.x >> 5;
    int nw = blockDim.x >> 5;
    #pragma unroll
    for (int o = 16; o; o >>= 1) {
        float t = __shfl_down_sync(0xffffffffu, v, o);
        v = ismax ? fmaxf(v, t) : v + t;
    }
    if (lane == 0) sh[w] = v;
    __syncthreads();
    if (w == 0) {
        v = (lane < nw) ? sh[lane] : (ismax ? -INFINITY : 0.f);
        #pragma unroll
        for (int o = 16; o; o >>= 1) {
            float t = __shfl_down_sync(0xffffffffu, v, o);
            v = ismax ? fmaxf(v, t) : v + t;
        }
        if (lane == 0) sh[0] = v;
    }
    __syncthreads();
    float r = sh[0];
    __syncthreads();
    return r;
}

__global__ void buildZ_kernel(const float* __restrict__ cls1, const float* __restrict__ cls2) {
    int id = blockIdx.x * 256 + threadIdx.x;
    if (id >= M_TOK * EMB) return;
    int e = id % EMB;
    int t = (id / EMB) % NTOK;
    int b = id / (EMB * NTOK);
    float v;
    if (t == 0)        v = cls2[e];
    else if (t < 197)  v = g_E2[(size_t)(b * NP + (t - 1)) * EMB + e];
    else if (t == 197) v = cls1[e];
    else               v = g_E1[(size_t)(b * NP + (t - 198)) * EMB + e];
    g_Z[id] = v;
}

__global__ void ln_split_kernel(const float* __restrict__ gam, const float* __restrict__ bet) {
    __shared__ float sh[8];
    int t = blockIdx.x, e = threadIdx.x;
    float v = g_Z[(size_t)t * EMB + e];
    float m = blockReduce(v, sh, false) * (1.f / EMB);
    float d = v - m;
    float var = blockReduce(d * d, sh, false) * (1.f / EMB);
    float y = d * rsqrtf(var + 1e-5f) * gam[e] + bet[e];
    __nv_bfloat16 hi, lo; split2(y, hi, lo);
    size_t base = (size_t)t * 768;
    g_Hs[base + e] = hi; g_Hs[base + 256 + e] = lo; g_Hs[base + 512 + e] = hi;
}

// Q: A-side [Qh|Ql|Qh]; K: B-side [Kh|Kh|Kl]
__global__ void convQK_kernel() {
    int id = blockIdx.x * 256 + threadIdx.x;
    if (id >= 256 * NTOK * 128) return;
    int d = id & 127;
    int rem = id >> 7;
    int t = rem % NTOK;
    int zz = rem / NTOK;
    int b = zz >> 1, h = zz & 1;
    size_t qrow = (size_t)(b * NTOK + t) * 768;
    float vq = g_QKV[qrow + h * 128 + d];
    float vk = g_QKV[qrow + 256 + h * 128 + d];
    size_t base = ((size_t)zz * NTOK + t) * 384;
    __nv_bfloat16 hi, lo;
    split2(vq, hi, lo);
    g_Qs[base + d] = hi; g_Qs[base + 128 + d] = lo; g_Qs[base + 256 + d] = hi;
    split2(vk, hi, lo);
    g_Ks[base + d] = hi; g_Ks[base + 128 + d] = hi; g_Ks[base + 256 + d] = lo;
}

// V transposed per-head, B-side [Vh|Vh|Vl], tokens padded to 448
__global__ void convV_kernel() {
    int id = blockIdx.x * 256 + threadIdx.x;
    if (id >= 256 * 128 * NT_PAD) return;
    int tc = id % NT_PAD;
    int rem = id / NT_PAD;
    int d = rem & 127;
    int zz = rem >> 7;
    int b = zz >> 1, h = zz & 1;
    float v = 0.f;
    if (tc < NTOK) v = g_QKV[(size_t)(b * NTOK + tc) * 768 + 512 + h * 128 + d];
    __nv_bfloat16 hi, lo; split2(v, hi, lo);
    size_t base = ((size_t)zz * 128 + d) * 1344;
    g_Vt[base + tc] = hi; g_Vt[base + 448 + tc] = hi; g_Vt[base + 896 + tc] = lo;
}

// softmax (/16) fused with A-side split [Ph|Pl|Ph], padded to 448
__global__ void softmax_split_kernel() {
    __shared__ float sh[8];
    int zz = blockIdx.y, q = blockIdx.x, tid = threadIdx.x;
    const float* row = g_S + ((size_t)zz * NTOK + q) * SLD;
    float mx = -INFINITY;
    for (int i = tid; i < NTOK; i += 128) mx = fmaxf(mx, row[i]);
    mx = blockReduce(mx, sh, true);
    float sum = 0.f;
    for (int i = tid; i < NTOK; i += 128) sum += expf(row[i] - mx);
    sum = blockReduce(sum, sh, false);
    float inv = 1.f / (sum * 16.f);
    __nv_bfloat16* prow = g_Ps + ((size_t)zz * NTOK + q) * 1344;
    for (int i = tid; i < NT_PAD; i += 128) {
        float p = (i < NTOK) ? expf(row[i] - mx) * inv : 0.f;
        __nv_bfloat16 hi, lo; split2(p, hi, lo);
        prow[i] = hi; prow[448 + i] = lo; prow[896 + i] = hi;
    }
}

__global__ void convA_kernel(const float* __restrict__ X, __nv_bfloat16* __restrict__ out,
                             int rows, int Kd) {
    int id = blockIdx.x * 256 + threadIdx.x;
    if (id >= rows * Kd) return;
    int k = id % Kd, rw = id / Kd;
    __nv_bfloat16 hi, lo; split2(X[(size_t)rw * Kd + k], hi, lo);
    size_t base = (size_t)rw * 3 * Kd;
    out[base + k] = hi; out[base + Kd + k] = lo; out[base + 2 * Kd + k] = hi;
}

__global__ void lnres_kernel(const float* __restrict__ gam, const float* __restrict__ bet) {
    __shared__ float sh[8];
    int t = blockIdx.x, e = threadIdx.x;
    float v = g_P[(size_t)t * EMB + e];
    float m = blockReduce(v, sh, false) * (1.f / EMB);
    float d = v - m;
    float var = blockReduce(d * d, sh, false) * (1.f / EMB);
    float o = d * rsqrtf(var + 1e-5f) * gam[e] + bet[e];
    g_Z2[(size_t)t * EMB + e] = g_Z[(size_t)t * EMB + e] + o;
}

__global__ void head_kernel(const float* __restrict__ gam, const float* __restrict__ bet,
                            const float* __restrict__ Wc, const float* __restrict__ bc,
                            float* __restrict__ out) {
    __shared__ float sh[8];
    int bb = blockIdx.x, e = threadIdx.x;
    const float* p = g_Z2 + (size_t)bb * NTOK * EMB + e;
    float s = 0.f;
    for (int t = 0; t < NTOK; t++) s += p[(size_t)t * EMB];
    float pooled = s * (1.f / NTOK);
    float m = blockReduce(pooled, sh, false) * (1.f / EMB);
    float d = pooled - m;
    float var = blockReduce(d * d, sh, false) * (1.f / EMB);
    float y = d * rsqrtf(var + 1e-5f) * gam[e] + bet[e];
    float p0 = blockReduce(y * Wc[e * 2 + 0], sh, false);
    float p1 = blockReduce(y * Wc[e * 2 + 1], sh, false);
    if (e == 0) {
        float l0 = p0 + bc[0], l1 = p1 + bc[1];
        float mm = fmaxf(l0, l1);
        float lse = mm + logf(expf(l0 - mm) + expf(l1 - mm));
        out[bb * 2 + 0] = l0 - lse;
        out[bb * 2 + 1] = l1 - lse;
    }
}

// ================ launch ================
extern "C" void kernel_launch(void* const* d_in, const int* in_sizes, int n_in,
                              void* d_out, int out_size)
{
    const float* x    = (const float*)d_in[0];
    const float* W1   = (const float*)d_in[1];
    const float* b1   = (const float*)d_in[2];
    const float* cls1 = (const float*)d_in[3];
    const float* W2   = (const float*)d_in[4];
    const float* b2   = (const float*)d_in[5];
    const float* cls2 = (const float*)d_in[6];
    const float* ln1g = (const float*)d_in[7];
    const float* ln1b = (const float*)d_in[8];
    const float* Wq   = (const float*)d_in[9];
    const float* bq   = (const float*)d_in[10];
    const float* Wk   = (const float*)d_in[11];
    const float* bk   = (const float*)d_in[12];
    const float* Wv   = (const float*)d_in[13];
    const float* bv   = (const float*)d_in[14];
    const float* Wp   = (const float*)d_in[15];
    const float* bp   = (const float*)d_in[16];
    const float* ln2g = (const float*)d_in[17];
    const float* ln2b = (const float*)d_in[18];
    const float* lncg = (const float*)d_in[19];
    const float* lncb = (const float*)d_in[20];
    const float* Wc   = (const float*)d_in[21];
    const float* bc   = (const float*)d_in[22];
    float* out = (float*)d_out;

    __nv_bfloat16 *A1, *A2, *W1T, *W2T, *WqkvT, *WpT, *Hs, *Qs, *Ks, *Vt, *Ps, *Os;
    float *bqkv, *E1, *E2, *QKV, *S, *O, *P;
    cudaGetSymbolAddress((void**)&A1, g_A1);
    cudaGetSymbolAddress((void**)&A2, g_A2);
    cudaGetSymbolAddress((void**)&W1T, g_W1T);
    cudaGetSymbolAddress((void**)&W2T, g_W2T);
    cudaGetSymbolAddress((void**)&WqkvT, g_WqkvT);
    cudaGetSymbolAddress((void**)&WpT, g_WpT);
    cudaGetSymbolAddress((void**)&bqkv, g_bqkv);
    cudaGetSymbolAddress((void**)&E1, g_E1);
    cudaGetSymbolAddress((void**)&E2, g_E2);
    cudaGetSymbolAddress((void**)&Hs, g_Hs);
    cudaGetSymbolAddress((void**)&QKV, g_QKV);
    cudaGetSymbolAddress((void**)&Qs, g_Qs);
    cudaGetSymbolAddress((void**)&Ks, g_Ks);
    cudaGetSymbolAddress((void**)&Vt, g_Vt);
    cudaGetSymbolAddress((void**)&S, g_S);
    cudaGetSymbolAddress((void**)&Ps, g_Ps);
    cudaGetSymbolAddress((void**)&O, g_O);
    cudaGetSymbolAddress((void**)&Os, g_Os);
    cudaGetSymbolAddress((void**)&P, g_P);

    // weight conversions
    convW_kernel<<<(768*256+255)/256, 256>>>(W1, W1T, 768, 256, 0, 2304);
    convW_kernel<<<(192*256+255)/256, 256>>>(W2, W2T, 192, 256, 0, 576);
    convW_kernel<<<(256*256+255)/256, 256>>>(Wq, WqkvT, 256, 256, 0, 768);
    convW_kernel<<<(256*256+255)/256, 256>>>(Wk, WqkvT, 256, 256, 256, 768);
    convW_kernel<<<(256*256+255)/256, 256>>>(Wv, WqkvT, 256, 256, 512, 768);
    convW_kernel<<<(256*768+255)/256, 256>>>(Wp, WpT, 256, 256, 0, 768);
    catBias_kernel<<<3, 256>>>(bq, bk, bv);

    // patch extract + split
    extract_split1<<<(M_PE*768+255)/256, 256>>>(x);
    extract_split2<<<(M_PE*192+255)/256, 256>>>(x);

    // patch-embed GEMMs
    gemm_mma<<<dim3(2,196,1), 256>>>(A1, W1T, b1, E1,
        M_PE, 256, 2304, 2304, 2304, 256, 0,0,0,0,0,0);
    gemm_mma<<<dim3(2,196,1), 256>>>(A2, W2T, b2, E2,
        M_PE, 256, 576, 576, 576, 256, 0,0,0,0,0,0);

    // assemble z, fused LN + split
    buildZ_kernel<<<(M_TOK*EMB+255)/256, 256>>>(cls1, cls2);
    ln_split_kernel<<<M_TOK, 256>>>(ln1g, ln1b);

    // fused QKV GEMM
    gemm_mma<<<dim3(6,394,1), 256>>>(Hs, WqkvT, bqkv, QKV,
        M_TOK, 768, 768, 768, 768, 768, 0,0,0,0,0,0);

    // per-head splits
    convQK_kernel<<<(256*NTOK*128+255)/256, 256>>>();
    convV_kernel<<<(256*128*NT_PAD+255)/256, 256>>>();

    // S = Q @ K^T (batched over 256 (b,h))
    gemm_mma<<<dim3(4,4,256), 256>>>(Qs, Ks, nullptr, S,
        NTOK, NTOK, 384, 384, 384, SLD,
        2L*NTOK*384, (long)NTOK*384, 2L*NTOK*384, (long)NTOK*384,
        2L*NTOK*SLD, (long)NTOK*SLD);

    // softmax + split
    softmax_split_kernel<<<dim3(NTOK, 256), 128>>>();

    // O = P @ V^T (batched)
    gemm_mma<<<dim3(1,4,256), 256>>>(Ps, Vt, nullptr, O,
        NTOK, 128, 1344, 1344, 1344, 256,
        2L*NTOK*1344, (long)NTOK*1344, 2L*128*1344, 128L*1344,
        (long)NTOK*256, 128L);

    // projection
    convA_kernel<<<(M_TOK*256+255)/256, 256>>>(O, Os, M_TOK, 256);
    gemm_mma<<<dim3(2,394,1), 256>>>(Os, WpT, bp, P,
        M_TOK, 256, 768, 768, 768, 256, 0,0,0,0,0,0);

    // residual + head
    lnres_kernel<<<M_TOK, 256>>>(ln2g, ln2b);
    head_kernel<<<BATCH, 256>>>(lncg, lncb, Wc, bc, out);
}

// round 5
// speedup vs baseline: 1.6084x; 1.1650x over previous
#include <cuda_runtime.h>
#include <cuda_bf16.h>
#include <cstdint>
#include <math.h>

#define BATCH 128
#define EMB   256
#define NTOK  394
#define NP    196
#define M_PE  (BATCH*NP)
#define M_TOK (BATCH*NTOK)
#define SLD   400
#define NT_PAD 448
#define AST   40

// ---------------- scratch (2-segment split storage: [hi|lo]) ----------------
__device__ __nv_bfloat16 g_A1[(size_t)M_PE*1536];
__device__ __nv_bfloat16 g_A2[(size_t)M_PE*384];
__device__ __nv_bfloat16 g_W1T[256*1536];
__device__ __nv_bfloat16 g_W2T[256*384];
__device__ __nv_bfloat16 g_WqkvT[768*512];
__device__ __nv_bfloat16 g_WpT[256*512];
__device__ float g_bqkv[768];
__device__ float g_E1[(size_t)M_PE*EMB];
__device__ float g_E2[(size_t)M_PE*EMB];
__device__ float g_Z [(size_t)M_TOK*EMB];
__device__ __nv_bfloat16 g_Hs[(size_t)M_TOK*512];
__device__ float g_QKV[(size_t)M_TOK*768];
__device__ __nv_bfloat16 g_Qs[(size_t)256*NTOK*256];
__device__ __nv_bfloat16 g_Ks[(size_t)256*NTOK*256];
__device__ __nv_bfloat16 g_Vt[(size_t)256*128*896];
__device__ float g_S [(size_t)256*NTOK*SLD];
__device__ __nv_bfloat16 g_Ps[(size_t)256*NTOK*896];
__device__ float g_O [(size_t)M_TOK*EMB];
__device__ __nv_bfloat16 g_Os[(size_t)M_TOK*512];
__device__ float g_P [(size_t)M_TOK*EMB];
__device__ float g_Z2[(size_t)M_TOK*EMB];

__device__ __forceinline__ uint32_t smem_u32(const void* p) {
    uint32_t a;
    asm("{ .reg .u64 t; cvta.to.shared.u64 t, %1; cvt.u32.u64 %0, t; }" : "=r"(a) : "l"(p));
    return a;
}
__device__ __forceinline__ void ldm4(uint32_t* r, uint32_t addr) {
    asm volatile("ldmatrix.sync.aligned.m8n8.x4.shared.b16 {%0,%1,%2,%3}, [%4];"
        : "=r"(r[0]), "=r"(r[1]), "=r"(r[2]), "=r"(r[3]) : "r"(addr));
}
__device__ __forceinline__ void mma16816(float* c, const uint32_t* a, uint32_t b0, uint32_t b1) {
    asm volatile(
        "mma.sync.aligned.m16n8k16.row.col.f32.bf16.bf16.f32 "
        "{%0,%1,%2,%3}, {%4,%5,%6,%7}, {%8,%9}, {%0,%1,%2,%3};"
        : "+f"(c[0]), "+f"(c[1]), "+f"(c[2]), "+f"(c[3])
        : "r"(a[0]), "r"(a[1]), "r"(a[2]), "r"(a[3]), "r"(b0), "r"(b1));
}
__device__ __forceinline__ void cp16(uint32_t dst, const void* src, bool pred) {
    int sz = pred ? 16 : 0;
    asm volatile("cp.async.cg.shared.global [%0], [%1], 16, %2;"
        :: "r"(dst), "l"(src), "r"(sz));
}
#define CP_COMMIT() asm volatile("cp.async.commit_group;" ::: "memory")
#define CP_WAIT0()  asm volatile("cp.async.wait_group 0;" ::: "memory")

// ============ warp-MMA GEMM with cp.async pipeline + wrap addressing ============
// C[M,N] = A[M,Kv] @ B[N,Kv]^T (+bias); stored A width = lda (<Kv), chunk offset
// koff >= awrap reads koff-awrap (duplicate segment). Same for B with bwrap.
__global__ void __launch_bounds__(256) gemm_mma(
    const __nv_bfloat16* __restrict__ Ag, const __nv_bfloat16* __restrict__ Bg,
    const float* __restrict__ bias, float* __restrict__ Cg,
    int M, int N, int K, int lda, int ldb, int ldc, int awrap, int bwrap,
    long sAz2, long sAz1, long sBz2, long sBz1, long sCz2, long sCz1)
{
    __shared__ __align__(16) __nv_bfloat16 As[2][128*AST];
    __shared__ __align__(16) __nv_bfloat16 Bs[2][128*AST];

    int tid = threadIdx.x, wid = tid >> 5, lane = tid & 31;
    int z = blockIdx.z;
    const __nv_bfloat16* A = Ag + (long)(z >> 1) * sAz2 + (long)(z & 1) * sAz1;
    const __nv_bfloat16* B = Bg + (long)(z >> 1) * sBz2 + (long)(z & 1) * sBz1;
    float* C = Cg + (long)(z >> 1) * sCz2 + (long)(z & 1) * sCz1;
    int row0 = blockIdx.y * 128, col0 = blockIdx.x * 128;
    A += (size_t)row0 * lda;
    B += (size_t)col0 * ldb;
    C += (size_t)row0 * ldc + col0;
    int Mrem = M - row0, Nrem = N - col0;

    int wm = wid & 3, wn = wid >> 2;      // warp tile 32(M) x 64(N)
    bool wact = (wm * 32 < Mrem) && (wn * 64 < Nrem);

    int ldrow = tid >> 1, half = tid & 1;
    bool aval = ldrow < Mrem, bval = ldrow < Nrem;
    const char* gaBase = reinterpret_cast<const char*>(A + (size_t)ldrow * lda) + half * 32;
    const char* gbBase = reinterpret_cast<const char*>(B + (size_t)ldrow * ldb) + half * 32;
    uint32_t sAb = smem_u32(&As[0][0]);
    uint32_t sBb = smem_u32(&Bs[0][0]);
    uint32_t sdstA = sAb + (ldrow * AST + half * 16) * 2;
    uint32_t sdstB = sBb + (ldrow * AST + half * 16) * 2;
    const uint32_t ABYTES = 128 * AST * 2;

    uint32_t aoff = ((wm * 32 + (lane & 15)) * AST + ((lane >> 4) * 8)) * 2;
    uint32_t boff = ((wn * 64 + (lane & 7) + ((lane >> 4) & 1) * 8) * AST) * 2
                  + ((lane >> 3) & 1) * 16;

    float acc[2][8][4];
    #pragma unroll
    for (int i = 0; i < 2; i++)
        #pragma unroll
        for (int j = 0; j < 8; j++)
            #pragma unroll
            for (int t = 0; t < 4; t++) acc[i][j][t] = 0.f;

    int nchunk = K >> 5;

    // prologue: chunk 0 -> buf 0
    {
        uint32_t dA = sdstA, dB = sdstB;
        cp16(dA, gaBase, aval); cp16(dA + 16, gaBase + 16, aval);
        cp16(dB, gbBase, bval); cp16(dB + 16, gbBase + 16, bval);
        CP_COMMIT();
    }
    CP_WAIT0();
    __syncthreads();

    for (int i = 0; i < nchunk; i++) {
        int s = i & 1;
        bool more = (i + 1) < nchunk;
        if (more) {
            int koff = (i + 1) * 32;
            int ka = koff >= awrap ? koff - awrap : koff;
            int kb = koff >= bwrap ? koff - bwrap : koff;
            uint32_t dA = sdstA + ((i + 1) & 1) * ABYTES;
            uint32_t dB = sdstB + ((i + 1) & 1) * ABYTES;
            const char* pA = gaBase + (size_t)ka * 2;
            const char* pB = gbBase + (size_t)kb * 2;
            cp16(dA, pA, aval); cp16(dA + 16, pA + 16, aval);
            cp16(dB, pB, bval); cp16(dB + 16, pB + 16, bval);
            CP_COMMIT();
        }
        if (wact) {
            uint32_t sA = sAb + s * ABYTES;
            uint32_t sB = sBb + s * ABYTES;
            #pragma unroll
            for (int kk = 0; kk < 2; kk++) {
                uint32_t a0[4], a1[4], bf[4][4];
                ldm4(a0, sA + aoff + kk * 32);
                ldm4(a1, sA + aoff + 16 * AST * 2 + kk * 32);
                #pragma unroll
                for (int j = 0; j < 4; j++)
                    ldm4(bf[j], sB + boff + j * 16 * AST * 2 + kk * 32);
                #pragma unroll
                for (int j = 0; j < 4; j++) {
                    mma16816(acc[0][2*j],   a0, bf[j][0], bf[j][1]);
                    mma16816(acc[0][2*j+1], a0, bf[j][2], bf[j][3]);
                    mma16816(acc[1][2*j],   a1, bf[j][0], bf[j][1]);
                    mma16816(acc[1][2*j+1], a1, bf[j][2], bf[j][3]);
                }
            }
        }
        if (more) {
            CP_WAIT0();
            __syncthreads();
        }
    }

    if (wact) {
        int grp = lane >> 2, qd = lane & 3;
        #pragma unroll
        for (int mt = 0; mt < 2; mt++) {
            int r0 = wm * 32 + mt * 16 + grp;
            #pragma unroll
            for (int nt = 0; nt < 8; nt++) {
                int c = wn * 64 + nt * 8 + qd * 2;
                float b0v = 0.f, b1v = 0.f;
                if (bias && c < Nrem) { b0v = bias[col0 + c]; }
                if (bias && c + 1 < Nrem) { b1v = bias[col0 + c + 1]; }
                if (r0 < Mrem) {
                    if (c < Nrem)     C[(size_t)r0 * ldc + c]     = acc[mt][nt][0] + b0v;
                    if (c + 1 < Nrem) C[(size_t)r0 * ldc + c + 1] = acc[mt][nt][1] + b1v;
                }
                if (r0 + 8 < Mrem) {
                    if (c < Nrem)     C[(size_t)(r0 + 8) * ldc + c]     = acc[mt][nt][2] + b0v;
                    if (c + 1 < Nrem) C[(size_t)(r0 + 8) * ldc + c + 1] = acc[mt][nt][3] + b1v;
                }
            }
        }
    }
}

// ================ conversion / pointwise kernels ================
__device__ __forceinline__ void split2(float v, __nv_bfloat16& hi, __nv_bfloat16& lo) {
    hi = __float2bfloat16(v);
    lo = __float2bfloat16(v - __bfloat162float(hi));
}

// W fp32 [K,N] -> row n: [hi(K)|lo(K)]
__global__ void convW_kernel(const float* __restrict__ W, __nv_bfloat16* __restrict__ out,
                             int K, int N, int nOff, int ldout) {
    int id = blockIdx.x * 256 + threadIdx.x;
    if (id >= K * N) return;
    int k = id / N, n = id % N;
    __nv_bfloat16 hi, lo; split2(W[(size_t)k * N + n], hi, lo);
    size_t base = (size_t)(nOff + n) * ldout;
    out[base + k] = hi; out[base + K + k] = lo;
}

__global__ void catBias_kernel(const float* a, const float* b, const float* c) {
    int i = blockIdx.x * 256 + threadIdx.x;
    if (i < 256) g_bqkv[i] = a[i];
    else if (i < 512) g_bqkv[i] = b[i - 256];
    else if (i < 768) g_bqkv[i] = c[i - 512];
}

__global__ void extract_split1(const float* __restrict__ x) {
    int id = blockIdx.x * 256 + threadIdx.x;
    if (id >= M_PE * 768) return;
    int col = id % 768, rw = id / 768;
    int b = rw / NP, pi = rw % NP;
    int ph = pi / 14, pw = pi % 14;
    int c = col % 3, s = col / 3;
    int pc = s % 16, pr = s / 16;
    float v = x[(size_t)(b * 3 + c) * 50176 + (ph * 16 + pr) * 224 + (pw * 16 + pc)];
    __nv_bfloat16 hi, lo; split2(v, hi, lo);
    size_t base = (size_t)rw * 1536;
    g_A1[base + col] = hi; g_A1[base + 768 + col] = lo;
}

__global__ void extract_split2(const float* __restrict__ x) {
    int id = blockIdx.x * 256 + threadIdx.x;
    if (id >= M_PE * 192) return;
    int col = id % 192, rw = id / 192;
    int b = rw / NP, j = rw % NP;
    int q = 4 * j + 3;
    int ph = q / 28, pw = q % 28;
    int c = col % 3, s = col / 3;
    int pc = s % 8, pr = s / 8;
    float v = x[(size_t)(b * 3 + c) * 50176 + (ph * 8 + pr) * 224 + (pw * 8 + pc)];
    __nv_bfloat16 hi, lo; split2(v, hi, lo);
    size_t base = (size_t)rw * 384;
    g_A2[base + col] = hi; g_A2[base + 192 + col] = lo;
}

__device__ __forceinline__ float blockReduce(float v, float* sh, bool ismax) {
    int lane = threadIdx.x & 31, w = threadIdx.x >> 5;
    int nw = blockDim.x >> 5;
    #pragma unroll
    for (int o = 16; o; o >>= 1) {
        float t = __shfl_down_sync(0xffffffffu, v, o);
        v = ismax ? fmaxf(v, t) : v + t;
    }
    if (lane == 0) sh[w] = v;
    __syncthreads();
    if (w == 0) {
        v = (lane < nw) ? sh[lane] : (ismax ? -INFINITY : 0.f);
        #pragma unroll
        for (int o = 16; o; o >>= 1) {
            float t = __shfl_down_sync(0xffffffffu, v, o);
            v = ismax ? fmaxf(v, t) : v + t;
        }
        if (lane == 0) sh[0] = v;
    }
    __syncthreads();
    float r = sh[0];
    __syncthreads();
    return r;
}

// fused: assemble z row, store g_Z, LN, split -> g_Hs [hi(256)|lo(256)]
__global__ void buildZ_ln_kernel(const float* __restrict__ cls1, const float* __restrict__ cls2,
                                 const float* __restrict__ gam, const float* __restrict__ bet) {
    __shared__ float sh[8];
    int tg = blockIdx.x, e = threadIdx.x;
    int t = tg % NTOK, b = tg / NTOK;
    float v;
    if (t == 0)        v = cls2[e];
    else if (t < 197)  v = g_E2[(size_t)(b * NP + (t - 1)) * EMB + e];
    else if (t == 197) v = cls1[e];
    else               v = g_E1[(size_t)(b * NP + (t - 198)) * EMB + e];
    g_Z[(size_t)tg * EMB + e] = v;
    float m = blockReduce(v, sh, false) * (1.f / EMB);
    float d = v - m;
    float var = blockReduce(d * d, sh, false) * (1.f / EMB);
    float y = d * rsqrtf(var + 1e-5f) * gam[e] + bet[e];
    __nv_bfloat16 hi, lo; split2(y, hi, lo);
    size_t base = (size_t)tg * 512;
    g_Hs[base + e] = hi; g_Hs[base + 256 + e] = lo;
}

// Q,K per-head: [hi(128)|lo(128)]
__global__ void convQK_kernel() {
    int id = blockIdx.x * 256 + threadIdx.x;
    if (id >= 256 * NTOK * 128) return;
    int d = id & 127;
    int rem = id >> 7;
    int t = rem % NTOK;
    int zz = rem / NTOK;
    int b = zz >> 1, h = zz & 1;
    size_t qrow = (size_t)(b * NTOK + t) * 768;
    float vq = g_QKV[qrow + h * 128 + d];
    float vk = g_QKV[qrow + 256 + h * 128 + d];
    size_t base = ((size_t)zz * NTOK + t) * 256;
    __nv_bfloat16 hi, lo;
    split2(vq, hi, lo);
    g_Qs[base + d] = hi; g_Qs[base + 128 + d] = lo;
    split2(vk, hi, lo);
    g_Ks[base + d] = hi; g_Ks[base + 128 + d] = lo;
}

// V transposed per-head: [hi(448)|lo(448)], tokens padded to 448
__global__ void convV_kernel() {
    int id = blockIdx.x * 256 + threadIdx.x;
    if (id >= 256 * 128 * NT_PAD) return;
    int tc = id % NT_PAD;
    int rem = id / NT_PAD;
    int d = rem & 127;
    int zz = rem >> 7;
    int b = zz >> 1, h = zz & 1;
    float v = 0.f;
    if (tc < NTOK) v = g_QKV[(size_t)(b * NTOK + tc) * 768 + 512 + h * 128 + d];
    __nv_bfloat16 hi, lo; split2(v, hi, lo);
    size_t base = ((size_t)zz * 128 + d) * 896;
    g_Vt[base + tc] = hi; g_Vt[base + 448 + tc] = lo;
}

// softmax (/16) fused with split: [hi(448)|lo(448)]
__global__ void softmax_split_kernel() {
    __shared__ float sh[8];
    int zz = blockIdx.y, q = blockIdx.x, tid = threadIdx.x;
    const float* row = g_S + ((size_t)zz * NTOK + q) * SLD;
    float mx = -INFINITY;
    for (int i = tid; i < NTOK; i += 128) mx = fmaxf(mx, row[i]);
    mx = blockReduce(mx, sh, true);
    float sum = 0.f;
    for (int i = tid; i < NTOK; i += 128) sum += expf(row[i] - mx);
    sum = blockReduce(sum, sh, false);
    float inv = 1.f / (sum * 16.f);
    __nv_bfloat16* prow = g_Ps + ((size_t)zz * NTOK + q) * 896;
    for (int i = tid; i < NT_PAD; i += 128) {
        float p = (i < NTOK) ? expf(row[i] - mx) * inv : 0.f;
        __nv_bfloat16 hi, lo; split2(p, hi, lo);
        prow[i] = hi; prow[448 + i] = lo;
    }
}

// fp32 [rows,Kd] -> [hi(Kd)|lo(Kd)]
__global__ void convA_kernel(const float* __restrict__ X, __nv_bfloat16* __restrict__ out,
                             int rows, int Kd) {
    int id = blockIdx.x * 256 + threadIdx.x;
    if (id >= rows * Kd) return;
    int k = id % Kd, rw = id / Kd;
    __nv_bfloat16 hi, lo; split2(X[(size_t)rw * Kd + k], hi, lo);
    size_t base = (size_t)rw * 2 * Kd;
    out[base + k] = hi; out[base + Kd + k] = lo;
}

__global__ void lnres_kernel(const float* __restrict__ gam, const float* __restrict__ bet) {
    __shared__ float sh[8];
    int t = blockIdx.x, e = threadIdx.x;
    float v = g_P[(size_t)t * EMB + e];
    float m = blockReduce(v, sh, false) * (1.f / EMB);
    float d = v - m;
    float var = blockReduce(d * d, sh, false) * (1.f / EMB);
    float o = d * rsqrtf(var + 1e-5f) * gam[e] + bet[e];
    g_Z2[(size_t)t * EMB + e] = g_Z[(size_t)t * EMB + e] + o;
}

__global__ void head_kernel(const float* __restrict__ gam, const float* __restrict__ bet,
                            const float* __restrict__ Wc, const float* __restrict__ bc,
                            float* __restrict__ out) {
    __shared__ float sh[8];
    int bb = blockIdx.x, e = threadIdx.x;
    const float* p = g_Z2 + (size_t)bb * NTOK * EMB + e;
    float s = 0.f;
    for (int t = 0; t < NTOK; t++) s += p[(size_t)t * EMB];
    float pooled = s * (1.f / NTOK);
    float m = blockReduce(pooled, sh, false) * (1.f / EMB);
    float d = pooled - m;
    float var = blockReduce(d * d, sh, false) * (1.f / EMB);
    float y = d * rsqrtf(var + 1e-5f) * gam[e] + bet[e];
    float p0 = blockReduce(y * Wc[e * 2 + 0], sh, false);
    float p1 = blockReduce(y * Wc[e * 2 + 1], sh, false);
    if (e == 0) {
        float l0 = p0 + bc[0], l1 = p1 + bc[1];
        float mm = fmaxf(l0, l1);
        float lse = mm + logf(expf(l0 - mm) + expf(l1 - mm));
        out[bb * 2 + 0] = l0 - lse;
        out[bb * 2 + 1] = l1 - lse;
    }
}

// ================ launch ================
extern "C" void kernel_launch(void* const* d_in, const int* in_sizes, int n_in,
                              void* d_out, int out_size)
{
    const float* x    = (const float*)d_in[0];
    const float* W1   = (const float*)d_in[1];
    const float* b1   = (const float*)d_in[2];
    const float* cls1 = (const float*)d_in[3];
    const float* W2   = (const float*)d_in[4];
    const float* b2   = (const float*)d_in[5];
    const float* cls2 = (const float*)d_in[6];
    const float* ln1g = (const float*)d_in[7];
    const float* ln1b = (const float*)d_in[8];
    const float* Wq   = (const float*)d_in[9];
    const float* bq   = (const float*)d_in[10];
    const float* Wk   = (const float*)d_in[11];
    const float* bk   = (const float*)d_in[12];
    const float* Wv   = (const float*)d_in[13];
    const float* bv   = (const float*)d_in[14];
    const float* Wp   = (const float*)d_in[15];
    const float* bp   = (const float*)d_in[16];
    const float* ln2g = (const float*)d_in[17];
    const float* ln2b = (const float*)d_in[18];
    const float* lncg = (const float*)d_in[19];
    const float* lncb = (const float*)d_in[20];
    const float* Wc   = (const float*)d_in[21];
    const float* bc   = (const float*)d_in[22];
    float* out = (float*)d_out;

    __nv_bfloat16 *A1, *A2, *W1T, *W2T, *WqkvT, *WpT, *Hs, *Qs, *Ks, *Vt, *Ps, *Os;
    float *bqkv, *E1, *E2, *QKV, *S, *O, *P;
    cudaGetSymbolAddress((void**)&A1, g_A1);
    cudaGetSymbolAddress((void**)&A2, g_A2);
    cudaGetSymbolAddress((void**)&W1T, g_W1T);
    cudaGetSymbolAddress((void**)&W2T, g_W2T);
    cudaGetSymbolAddress((void**)&WqkvT, g_WqkvT);
    cudaGetSymbolAddress((void**)&WpT, g_WpT);
    cudaGetSymbolAddress((void**)&bqkv, g_bqkv);
    cudaGetSymbolAddress((void**)&E1, g_E1);
    cudaGetSymbolAddress((void**)&E2, g_E2);
    cudaGetSymbolAddress((void**)&Hs, g_Hs);
    cudaGetSymbolAddress((void**)&QKV, g_QKV);
    cudaGetSymbolAddress((void**)&Qs, g_Qs);
    cudaGetSymbolAddress((void**)&Ks, g_Ks);
    cudaGetSymbolAddress((void**)&Vt, g_Vt);
    cudaGetSymbolAddress((void**)&S, g_S);
    cudaGetSymbolAddress((void**)&Ps, g_Ps);
    cudaGetSymbolAddress((void**)&O, g_O);
    cudaGetSymbolAddress((void**)&Os, g_Os);
    cudaGetSymbolAddress((void**)&P, g_P);

    // weight conversions ([hi|lo] layout)
    convW_kernel<<<(768*256+255)/256, 256>>>(W1, W1T, 768, 256, 0, 1536);
    convW_kernel<<<(192*256+255)/256, 256>>>(W2, W2T, 192, 256, 0, 384);
    convW_kernel<<<(256*256+255)/256, 256>>>(Wq, WqkvT, 256, 256, 0, 512);
    convW_kernel<<<(256*256+255)/256, 256>>>(Wk, WqkvT, 256, 256, 256, 512);
    convW_kernel<<<(256*256+255)/256, 256>>>(Wv, WqkvT, 256, 256, 512, 512);
    convW_kernel<<<(256*768+255)/256, 256>>>(Wp, WpT, 256, 256, 0, 512);
    catBias_kernel<<<3, 256>>>(bq, bk, bv);

    // patch extract + split
    extract_split1<<<(M_PE*768+255)/256, 256>>>(x);
    extract_split2<<<(M_PE*192+255)/256, 256>>>(x);

    // patch-embed GEMMs (virtual K = 3*Kreal)
    gemm_mma<<<dim3(2,196,1), 256>>>(A1, W1T, b1, E1,
        M_PE, 256, 2304, 1536, 1536, 256, 1536, 768, 0,0,0,0,0,0);
    gemm_mma<<<dim3(2,196,1), 256>>>(A2, W2T, b2, E2,
        M_PE, 256, 576, 384, 384, 256, 384, 192, 0,0,0,0,0,0);

    // fused z-assembly + LN + split
    buildZ_ln_kernel<<<M_TOK, 256>>>(cls1, cls2, ln1g, ln1b);

    // fused QKV GEMM
    gemm_mma<<<dim3(6,394,1), 256>>>(Hs, WqkvT, bqkv, QKV,
        M_TOK, 768, 768, 512, 512, 768, 512, 256, 0,0,0,0,0,0);

    // per-head splits
    convQK_kernel<<<(256*NTOK*128+255)/256, 256>>>();
    convV_kernel<<<(256*128*NT_PAD+255)/256, 256>>>();

    // S = Q @ K^T (batched over 256 (b,h))
    gemm_mma<<<dim3(4,4,256), 256>>>(Qs, Ks, nullptr, S,
        NTOK, NTOK, 384, 256, 256, SLD, 256, 128,
        2L*NTOK*256, (long)NTOK*256, 2L*NTOK*256, (long)NTOK*256,
        2L*NTOK*SLD, (long)NTOK*SLD);

    // softmax + split
    softmax_split_kernel<<<dim3(NTOK, 256), 128>>>();

    // O = P @ V^T (batched)
    gemm_mma<<<dim3(1,4,256), 256>>>(Ps, Vt, nullptr, O,
        NTOK, 128, 1344, 896, 896, 256, 896, 448,
        2L*NTOK*896, (long)NTOK*896, 2L*128*896, 128L*896,
        (long)NTOK*256, 128L);

    // projection
    convA_kernel<<<(M_TOK*256+255)/256, 256>>>(O, Os, M_TOK, 256);
    gemm_mma<<<dim3(2,394,1), 256>>>(Os, WpT, bp, P,
        M_TOK, 256, 768, 512, 512, 256, 512, 256, 0,0,0,0,0,0);

    // residual + head
    lnres_kernel<<<M_TOK, 256>>>(ln2g, ln2b);
    head_kernel<<<BATCH, 256>>>(lncg, lncb, Wc, bc, out);
}

// round 6
// speedup vs baseline: 1.6576x; 1.0306x over previous
#include <cuda_runtime.h>
#include <cuda_bf16.h>
#include <cstdint>
#include <math.h>

#define BATCH 128
#define EMB   256
#define NTOK  394
#define NP    196
#define M_PE  (BATCH*NP)
#define M_TOK (BATCH*NTOK)
#define SLD   400
#define NT_PAD 448
#define AST   40
#define TILEB (128*AST*2)          // 10240 B per operand tile per stage
#define GSMEM (3*2*TILEB)          // 61440 B dynamic smem

// ---------------- scratch ([hi|lo] split storage) ----------------
__device__ __nv_bfloat16 g_A1[(size_t)M_PE*1536];
__device__ __nv_bfloat16 g_A2[(size_t)M_PE*384];
__device__ __nv_bfloat16 g_W1T[256*1536];
__device__ __nv_bfloat16 g_W2T[256*384];
__device__ __nv_bfloat16 g_WqkvT[768*512];
__device__ __nv_bfloat16 g_WpT[256*512];
__device__ float g_bqkv[768];
__device__ float g_E1[(size_t)M_PE*EMB];
__device__ float g_E2[(size_t)M_PE*EMB];
__device__ float g_Z [(size_t)M_TOK*EMB];
__device__ __nv_bfloat16 g_Hs[(size_t)M_TOK*512];
__device__ float g_QKV[(size_t)M_TOK*768];
__device__ __nv_bfloat16 g_Qs[(size_t)256*NTOK*256];
__device__ __nv_bfloat16 g_Ks[(size_t)256*NTOK*256];
__device__ __nv_bfloat16 g_Vt[(size_t)256*128*896];
__device__ float g_S [(size_t)256*NTOK*SLD];
__device__ __nv_bfloat16 g_Ps[(size_t)256*NTOK*896];
__device__ float g_O [(size_t)M_TOK*EMB];
__device__ __nv_bfloat16 g_Os[(size_t)M_TOK*512];
__device__ float g_P [(size_t)M_TOK*EMB];
__device__ float g_Z2[(size_t)M_TOK*EMB];

__device__ __forceinline__ uint32_t smem_u32(const void* p) {
    uint32_t a;
    asm("{ .reg .u64 t; cvta.to.shared.u64 t, %1; cvt.u32.u64 %0, t; }" : "=r"(a) : "l"(p));
    return a;
}
__device__ __forceinline__ void ldm4(uint32_t* r, uint32_t addr) {
    asm volatile("ldmatrix.sync.aligned.m8n8.x4.shared.b16 {%0,%1,%2,%3}, [%4];"
        : "=r"(r[0]), "=r"(r[1]), "=r"(r[2]), "=r"(r[3]) : "r"(addr));
}
__device__ __forceinline__ void mma16816(float* c, const uint32_t* a, uint32_t b0, uint32_t b1) {
    asm volatile(
        "mma.sync.aligned.m16n8k16.row.col.f32.bf16.bf16.f32 "
        "{%0,%1,%2,%3}, {%4,%5,%6,%7}, {%8,%9}, {%0,%1,%2,%3};"
        : "+f"(c[0]), "+f"(c[1]), "+f"(c[2]), "+f"(c[3])
        : "r"(a[0]), "r"(a[1]), "r"(a[2]), "r"(a[3]), "r"(b0), "r"(b1));
}
__device__ __forceinline__ void cp16(uint32_t dst, const void* src, bool pred) {
    int sz = pred ? 16 : 0;
    asm volatile("cp.async.cg.shared.global [%0], [%1], 16, %2;"
        :: "r"(dst), "l"(src), "r"(sz));
}
#define CP_COMMIT() asm volatile("cp.async.commit_group;" ::: "memory")
#define CP_WAIT0()  asm volatile("cp.async.wait_group 0;" ::: "memory")
#define CP_WAIT1()  asm volatile("cp.async.wait_group 1;" ::: "memory")

// ============ warp-MMA GEMM, 3-stage cp.async pipeline + wrap addressing ============
// C[M,N] = A[M,Kv] @ B[N,Kv]^T (+bias); stored K width = lda; chunk k-offset
// >= awrap reads offset-awrap (duplicated hi segment). Batched over blockIdx.z.
__global__ void __launch_bounds__(256) gemm_mma(
    const __nv_bfloat16* __restrict__ Ag, const __nv_bfloat16* __restrict__ Bg,
    const float* __restrict__ bias, float* __restrict__ Cg,
    int M, int N, int K, int lda, int ldb, int ldc, int awrap, int bwrap,
    long sAz2, long sAz1, long sBz2, long sBz1, long sCz2, long sCz1)
{
    extern __shared__ char sm[];
    uint32_t sbase = smem_u32(sm);

    int tid = threadIdx.x, wid = tid >> 5, lane = tid & 31;
    int z = blockIdx.z;
    const __nv_bfloat16* A = Ag + (long)(z >> 1) * sAz2 + (long)(z & 1) * sAz1;
    const __nv_bfloat16* B = Bg + (long)(z >> 1) * sBz2 + (long)(z & 1) * sBz1;
    float* C = Cg + (long)(z >> 1) * sCz2 + (long)(z & 1) * sCz1;
    int row0 = blockIdx.y * 128, col0 = blockIdx.x * 128;
    A += (size_t)row0 * lda;
    B += (size_t)col0 * ldb;
    C += (size_t)row0 * ldc + col0;
    int Mrem = M - row0, Nrem = N - col0;

    int wm = wid & 3, wn = wid >> 2;     // warp tile 32(M) x 64(N)
    bool wact = (wm * 32 < Mrem) && (wn * 64 < Nrem);

    int ldrow = tid >> 1, half = tid & 1;
    bool aval = ldrow < Mrem, bval = ldrow < Nrem;
    const char* gaBase = reinterpret_cast<const char*>(A + (size_t)ldrow * lda) + half * 32;
    const char* gbBase = reinterpret_cast<const char*>(B + (size_t)ldrow * ldb) + half * 32;
    uint32_t dstOff = (ldrow * AST + half * 16) * 2;

    uint32_t aoff = ((wm * 32 + (lane & 15)) * AST + ((lane >> 4) * 8)) * 2;
    uint32_t boff = ((wn * 64 + (lane & 7) + ((lane >> 4) & 1) * 8) * AST) * 2
                  + ((lane >> 3) & 1) * 16;

    float acc[2][8][4];
    #pragma unroll
    for (int i = 0; i < 2; i++)
        #pragma unroll
        for (int j = 0; j < 8; j++)
            #pragma unroll
            for (int t = 0; t < 4; t++) acc[i][j][t] = 0.f;

    int nchunk = K >> 5;

    // prologue: chunks 0,1 -> stages 0,1
    {
        uint32_t dA = sbase + dstOff, dB = sbase + TILEB + dstOff;
        cp16(dA, gaBase, aval); cp16(dA + 16, gaBase + 16, aval);
        cp16(dB, gbBase, bval); cp16(dB + 16, gbBase + 16, bval);
        CP_COMMIT();
    }
    if (nchunk > 1) {
        int koff = 32;
        int ka = koff >= awrap ? koff - awrap : koff;
        int kb = koff >= bwrap ? koff - bwrap : koff;
        uint32_t dA = sbase + 2 * TILEB + dstOff, dB = sbase + 3 * TILEB + dstOff;
        cp16(dA, gaBase + (size_t)ka * 2, aval);
        cp16(dA + 16, gaBase + (size_t)ka * 2 + 16, aval);
        cp16(dB, gbBase + (size_t)kb * 2, bval);
        cp16(dB + 16, gbBase + (size_t)kb * 2 + 16, bval);
        CP_COMMIT();
    }

    for (int i = 0; i < nchunk; i++) {
        if (i + 1 < nchunk) { CP_WAIT1(); } else { CP_WAIT0(); }
        __syncthreads();

        int st = i % 3;
        uint32_t sA = sbase + st * 2 * TILEB;
        uint32_t sB = sA + TILEB;
        if (wact) {
            #pragma unroll
            for (int kk = 0; kk < 2; kk++) {
                uint32_t a0[4], a1[4], bf[4][4];
                ldm4(a0, sA + aoff + kk * 32);
                ldm4(a1, sA + aoff + 16 * AST * 2 + kk * 32);
                #pragma unroll
                for (int j = 0; j < 4; j++)
                    ldm4(bf[j], sB + boff + j * 16 * AST * 2 + kk * 32);
                #pragma unroll
                for (int j = 0; j < 4; j++) {
                    mma16816(acc[0][2*j],   a0, bf[j][0], bf[j][1]);
                    mma16816(acc[0][2*j+1], a0, bf[j][2], bf[j][3]);
                    mma16816(acc[1][2*j],   a1, bf[j][0], bf[j][1]);
                    mma16816(acc[1][2*j+1], a1, bf[j][2], bf[j][3]);
                }
            }
        }
        if (i + 2 < nchunk) {
            int koff = (i + 2) * 32;
            int ka = koff >= awrap ? koff - awrap : koff;
            int kb = koff >= bwrap ? koff - bwrap : koff;
            int st2 = (i + 2) % 3;
            uint32_t dA = sbase + st2 * 2 * TILEB + dstOff;
            uint32_t dB = dA + TILEB;
            cp16(dA, gaBase + (size_t)ka * 2, aval);
            cp16(dA + 16, gaBase + (size_t)ka * 2 + 16, aval);
            cp16(dB, gbBase + (size_t)kb * 2, bval);
            cp16(dB + 16, gbBase + (size_t)kb * 2 + 16, bval);
            CP_COMMIT();
        }
    }

    if (wact) {
        int grp = lane >> 2, qd = lane & 3;
        #pragma unroll
        for (int mt = 0; mt < 2; mt++) {
            int r0 = wm * 32 + mt * 16 + grp;
            #pragma unroll
            for (int nt = 0; nt < 8; nt++) {
                int c = wn * 64 + nt * 8 + qd * 2;
                float b0v = 0.f, b1v = 0.f;
                if (bias && c < Nrem)     b0v = bias[col0 + c];
                if (bias && c + 1 < Nrem) b1v = bias[col0 + c + 1];
                if (r0 < Mrem) {
                    if (c < Nrem)     C[(size_t)r0 * ldc + c]     = acc[mt][nt][0] + b0v;
                    if (c + 1 < Nrem) C[(size_t)r0 * ldc + c + 1] = acc[mt][nt][1] + b1v;
                }
                if (r0 + 8 < Mrem) {
                    if (c < Nrem)     C[(size_t)(r0 + 8) * ldc + c]     = acc[mt][nt][2] + b0v;
                    if (c + 1 < Nrem) C[(size_t)(r0 + 8) * ldc + c + 1] = acc[mt][nt][3] + b1v;
                }
            }
        }
    }
}

// ================ conversion / pointwise kernels ================
__device__ __forceinline__ void split2(float v, __nv_bfloat16& hi, __nv_bfloat16& lo) {
    hi = __float2bfloat16(v);
    lo = __float2bfloat16(v - __bfloat162float(hi));
}

__device__ __forceinline__ void convW_one(const float* W, __nv_bfloat16* out,
                                          int K, int N, int id, int nOff, int ldout) {
    int k = id / N, n = id % N;
    __nv_bfloat16 hi, lo; split2(W[(size_t)k * N + n], hi, lo);
    size_t base = (size_t)(nOff + n) * ldout;
    out[base + k] = hi; out[base + K + k] = lo;
}

// all 6 weight conversions + bias concat in one kernel
__global__ void convAll_kernel(const float* __restrict__ W1, const float* __restrict__ W2,
                               const float* __restrict__ Wq, const float* __restrict__ Wk,
                               const float* __restrict__ Wv, const float* __restrict__ Wp,
                               const float* __restrict__ bq, const float* __restrict__ bk,
                               const float* __restrict__ bv) {
    int id = blockIdx.x * 256 + threadIdx.x;
    if (id < 196608) { convW_one(W1, g_W1T, 768, 256, id, 0, 1536); return; }
    id -= 196608;
    if (id < 49152)  { convW_one(W2, g_W2T, 192, 256, id, 0, 384); return; }
    id -= 49152;
    if (id < 65536)  { convW_one(Wq, g_WqkvT, 256, 256, id, 0, 512); return; }
    id -= 65536;
    if (id < 65536)  { convW_one(Wk, g_WqkvT, 256, 256, id, 256, 512); return; }
    id -= 65536;
    if (id < 65536)  { convW_one(Wv, g_WqkvT, 256, 256, id, 512, 512); return; }
    id -= 65536;
    if (id < 65536)  { convW_one(Wp, g_WpT, 256, 256, id, 0, 512); return; }
    id -= 65536;
    if (id < 768) {
        float v = (id < 256) ? bq[id] : (id < 512 ? bk[id - 256] : bv[id - 512]);
        g_bqkv[id] = v;
    }
}

// both patch extracts + split in one kernel
__global__ void extractBoth_kernel(const float* __restrict__ x) {
    int id = blockIdx.x * 256 + threadIdx.x;
    if (id < M_PE * 768) {
        int col = id % 768, rw = id / 768;
        int b = rw / NP, pi = rw % NP;
        int ph = pi / 14, pw = pi % 14;
        int c = col % 3, s = col / 3;
        int pc = s % 16, pr = s / 16;
        float v = x[(size_t)(b * 3 + c) * 50176 + (ph * 16 + pr) * 224 + (pw * 16 + pc)];
        __nv_bfloat16 hi, lo; split2(v, hi, lo);
        size_t base = (size_t)rw * 1536;
        g_A1[base + col] = hi; g_A1[base + 768 + col] = lo;
        return;
    }
    id -= M_PE * 768;
    if (id < M_PE * 192) {
        int col = id % 192, rw = id / 192;
        int b = rw / NP, j = rw % NP;
        int q = 4 * j + 3;
        int ph = q / 28, pw = q % 28;
        int c = col % 3, s = col / 3;
        int pc = s % 8, pr = s / 8;
        float v = x[(size_t)(b * 3 + c) * 50176 + (ph * 8 + pr) * 224 + (pw * 8 + pc)];
        __nv_bfloat16 hi, lo; split2(v, hi, lo);
        size_t base = (size_t)rw * 384;
        g_A2[base + col] = hi; g_A2[base + 192 + col] = lo;
    }
}

__device__ __forceinline__ float blockReduce(float v, float* sh, bool ismax) {
    int lane = threadIdx.x & 31, w = threadIdx.x >> 5;
    int nw = blockDim.x >> 5;
    #pragma unroll
    for (int o = 16; o; o >>= 1) {
        float t = __shfl_down_sync(0xffffffffu, v, o);
        v = ismax ? fmaxf(v, t) : v + t;
    }
    if (lane == 0) sh[w] = v;
    __syncthreads();
    if (w == 0) {
        v = (lane < nw) ? sh[lane] : (ismax ? -INFINITY : 0.f);
        #pragma unroll
        for (int o = 16; o; o >>= 1) {
            float t = __shfl_down_sync(0xffffffffu, v, o);
            v = ismax ? fmaxf(v, t) : v + t;
        }
        if (lane == 0) sh[0] = v;
    }
    __syncthreads();
    float r = sh[0];
    __syncthreads();
    return r;
}

__global__ void buildZ_ln_kernel(const float* __restrict__ cls1, const float* __restrict__ cls2,
                                 const float* __restrict__ gam, const float* __restrict__ bet) {
    __shared__ float sh[8];
    int tg = blockIdx.x, e = threadIdx.x;
    int t = tg % NTOK, b = tg / NTOK;
    float v;
    if (t == 0)        v = cls2[e];
    else if (t < 197)  v = g_E2[(size_t)(b * NP + (t - 1)) * EMB + e];
    else if (t == 197) v = cls1[e];
    else               v = g_E1[(size_t)(b * NP + (t - 198)) * EMB + e];
    g_Z[(size_t)tg * EMB + e] = v;
    float m = blockReduce(v, sh, false) * (1.f / EMB);
    float d = v - m;
    float var = blockReduce(d * d, sh, false) * (1.f / EMB);
    float y = d * rsqrtf(var + 1e-5f) * gam[e] + bet[e];
    __nv_bfloat16 hi, lo; split2(y, hi, lo);
    size_t base = (size_t)tg * 512;
    g_Hs[base + e] = hi; g_Hs[base + 256 + e] = lo;
}

__global__ void convQK_kernel() {
    int id = blockIdx.x * 256 + threadIdx.x;
    if (id >= 256 * NTOK * 128) return;
    int d = id & 127;
    int rem = id >> 7;
    int t = rem % NTOK;
    int zz = rem / NTOK;
    int b = zz >> 1, h = zz & 1;
    size_t qrow = (size_t)(b * NTOK + t) * 768;
    float vq = g_QKV[qrow + h * 128 + d];
    float vk = g_QKV[qrow + 256 + h * 128 + d];
    size_t base = ((size_t)zz * NTOK + t) * 256;
    __nv_bfloat16 hi, lo;
    split2(vq, hi, lo);
    g_Qs[base + d] = hi; g_Qs[base + 128 + d] = lo;
    split2(vk, hi, lo);
    g_Ks[base + d] = hi; g_Ks[base + 128 + d] = lo;
}

// V transpose via smem tile: grid(14, 4, 256), block(32,8)
__global__ void convV_kernel() {
    __shared__ float tile[32][33];
    int zz = blockIdx.z;
    int d0 = blockIdx.y * 32, t0 = blockIdx.x * 32;
    int b = zz >> 1, h = zz & 1;
    int tx = threadIdx.x, ty = threadIdx.y;
    #pragma unroll
    for (int r = ty; r < 32; r += 8) {
        int tc = t0 + r;
        float v = 0.f;
        if (tc < NTOK)
            v = g_QKV[(size_t)(b * NTOK + tc) * 768 + 512 + h * 128 + d0 + tx];
        tile[r][tx] = v;
    }
    __syncthreads();
    #pragma unroll
    for (int r = ty; r < 32; r += 8) {
        int d = d0 + r;
        size_t base = ((size_t)zz * 128 + d) * 896;
        float v = tile[tx][r];
        __nv_bfloat16 hi, lo; split2(v, hi, lo);
        int tc = t0 + tx;
        g_Vt[base + tc] = hi; g_Vt[base + 448 + tc] = lo;
    }
}

__global__ void softmax_split_kernel() {
    __shared__ float sh[8];
    int zz = blockIdx.y, q = blockIdx.x, tid = threadIdx.x;
    const float* row = g_S + ((size_t)zz * NTOK + q) * SLD;
    float mx = -INFINITY;
    for (int i = tid; i < NTOK; i += 128) mx = fmaxf(mx, row[i]);
    mx = blockReduce(mx, sh, true);
    float sum = 0.f;
    for (int i = tid; i < NTOK; i += 128) sum += expf(row[i] - mx);
    sum = blockReduce(sum, sh, false);
    float inv = 1.f / (sum * 16.f);
    __nv_bfloat16* prow = g_Ps + ((size_t)zz * NTOK + q) * 896;
    for (int i = tid; i < NT_PAD; i += 128) {
        float p = (i < NTOK) ? expf(row[i] - mx) * inv : 0.f;
        __nv_bfloat16 hi, lo; split2(p, hi, lo);
        prow[i] = hi; prow[448 + i] = lo;
    }
}

__global__ void convA_kernel(const float* __restrict__ X, __nv_bfloat16* __restrict__ out,
                             int rows, int Kd) {
    int id = blockIdx.x * 256 + threadIdx.x;
    if (id >= rows * Kd) return;
    int k = id % Kd, rw = id / Kd;
    __nv_bfloat16 hi, lo; split2(X[(size_t)rw * Kd + k], hi, lo);
    size_t base = (size_t)rw * 2 * Kd;
    out[base + k] = hi; out[base + Kd + k] = lo;
}

__global__ void lnres_kernel(const float* __restrict__ gam, const float* __restrict__ bet) {
    __shared__ float sh[8];
    int t = blockIdx.x, e = threadIdx.x;
    float v = g_P[(size_t)t * EMB + e];
    float m = blockReduce(v, sh, false) * (1.f / EMB);
    float d = v - m;
    float var = blockReduce(d * d, sh, false) * (1.f / EMB);
    float o = d * rsqrtf(var + 1e-5f) * gam[e] + bet[e];
    g_Z2[(size_t)t * EMB + e] = g_Z[(size_t)t * EMB + e] + o;
}

__global__ void head_kernel(const float* __restrict__ gam, const float* __restrict__ bet,
                            const float* __restrict__ Wc, const float* __restrict__ bc,
                            float* __restrict__ out) {
    __shared__ float sh[8];
    int bb = blockIdx.x, e = threadIdx.x;
    const float* p = g_Z2 + (size_t)bb * NTOK * EMB + e;
    float s = 0.f;
    for (int t = 0; t < NTOK; t++) s += p[(size_t)t * EMB];
    float pooled = s * (1.f / NTOK);
    float m = blockReduce(pooled, sh, false) * (1.f / EMB);
    float d = pooled - m;
    float var = blockReduce(d * d, sh, false) * (1.f / EMB);
    float y = d * rsqrtf(var + 1e-5f) * gam[e] + bet[e];
    float p0 = blockReduce(y * Wc[e * 2 + 0], sh, false);
    float p1 = blockReduce(y * Wc[e * 2 + 1], sh, false);
    if (e == 0) {
        float l0 = p0 + bc[0], l1 = p1 + bc[1];
        float mm = fmaxf(l0, l1);
        float lse = mm + logf(expf(l0 - mm) + expf(l1 - mm));
        out[bb * 2 + 0] = l0 - lse;
        out[bb * 2 + 1] = l1 - lse;
    }
}

// ================ launch ================
extern "C" void kernel_launch(void* const* d_in, const int* in_sizes, int n_in,
                              void* d_out, int out_size)
{
    const float* x    = (const float*)d_in[0];
    const float* W1   = (const float*)d_in[1];
    const float* b1   = (const float*)d_in[2];
    const float* cls1 = (const float*)d_in[3];
    const float* W2   = (const float*)d_in[4];
    const float* b2   = (const float*)d_in[5];
    const float* cls2 = (const float*)d_in[6];
    const float* ln1g = (const float*)d_in[7];
    const float* ln1b = (const float*)d_in[8];
    const float* Wq   = (const float*)d_in[9];
    const float* bq   = (const float*)d_in[10];
    const float* Wk   = (const float*)d_in[11];
    const float* bk   = (const float*)d_in[12];
    const float* Wv   = (const float*)d_in[13];
    const float* bv   = (const float*)d_in[14];
    const float* Wp   = (const float*)d_in[15];
    const float* bp   = (const float*)d_in[16];
    const float* ln2g = (const float*)d_in[17];
    const float* ln2b = (const float*)d_in[18];
    const float* lncg = (const float*)d_in[19];
    const float* lncb = (const float*)d_in[20];
    const float* Wc   = (const float*)d_in[21];
    const float* bc   = (const float*)d_in[22];
    float* out = (float*)d_out;

    __nv_bfloat16 *A1, *A2, *W1T, *W2T, *WqkvT, *WpT, *Hs, *Qs, *Ks, *Vt, *Ps, *Os;
    float *bqkv, *E1, *E2, *QKV, *S, *O, *P;
    cudaGetSymbolAddress((void**)&A1, g_A1);
    cudaGetSymbolAddress((void**)&A2, g_A2);
    cudaGetSymbolAddress((void**)&W1T, g_W1T);
    cudaGetSymbolAddress((void**)&W2T, g_W2T);
    cudaGetSymbolAddress((void**)&WqkvT, g_WqkvT);
    cudaGetSymbolAddress((void**)&WpT, g_WpT);
    cudaGetSymbolAddress((void**)&bqkv, g_bqkv);
    cudaGetSymbolAddress((void**)&E1, g_E1);
    cudaGetSymbolAddress((void**)&E2, g_E2);
    cudaGetSymbolAddress((void**)&Hs, g_Hs);
    cudaGetSymbolAddress((void**)&QKV, g_QKV);
    cudaGetSymbolAddress((void**)&Qs, g_Qs);
    cudaGetSymbolAddress((void**)&Ks, g_Ks);
    cudaGetSymbolAddress((void**)&Vt, g_Vt);
    cudaGetSymbolAddress((void**)&S, g_S);
    cudaGetSymbolAddress((void**)&Ps, g_Ps);
    cudaGetSymbolAddress((void**)&O, g_O);
    cudaGetSymbolAddress((void**)&Os, g_Os);
    cudaGetSymbolAddress((void**)&P, g_P);

    cudaFuncSetAttribute(gemm_mma, cudaFuncAttributeMaxDynamicSharedMemorySize, GSMEM);

    // 1: all weight conversions
    convAll_kernel<<<(508672 + 255)/256, 256>>>(W1, W2, Wq, Wk, Wv, Wp, bq, bk, bv);
    // 2: both patch extracts
    extractBoth_kernel<<<(M_PE*960 + 255)/256, 256>>>(x);
    // 3,4: patch-embed GEMMs
    gemm_mma<<<dim3(2,196,1), 256, GSMEM>>>(A1, W1T, b1, E1,
        M_PE, 256, 2304, 1536, 1536, 256, 1536, 768, 0,0,0,0,0,0);
    gemm_mma<<<dim3(2,196,1), 256, GSMEM>>>(A2, W2T, b2, E2,
        M_PE, 256, 576, 384, 384, 256, 384, 192, 0,0,0,0,0,0);
    // 5: fused z-assembly + LN + split
    buildZ_ln_kernel<<<M_TOK, 256>>>(cls1, cls2, ln1g, ln1b);
    // 6: fused QKV GEMM  (ncu profiles this one)
    gemm_mma<<<dim3(6,394,1), 256, GSMEM>>>(Hs, WqkvT, bqkv, QKV,
        M_TOK, 768, 768, 512, 512, 768, 512, 256, 0,0,0,0,0,0);
    // 7,8: per-head splits
    convQK_kernel<<<(256*NTOK*128 + 255)/256, 256>>>();
    convV_kernel<<<dim3(14, 4, 256), dim3(32, 8)>>>();
    // 9: S = Q @ K^T
    gemm_mma<<<dim3(4,4,256), 256, GSMEM>>>(Qs, Ks, nullptr, S,
        NTOK, NTOK, 384, 256, 256, SLD, 256, 128,
        2L*NTOK*256, (long)NTOK*256, 2L*NTOK*256, (long)NTOK*256,
        2L*NTOK*SLD, (long)NTOK*SLD);
    // 10: softmax + split
    softmax_split_kernel<<<dim3(NTOK, 256), 128>>>();
    // 11: O = P @ V^T
    gemm_mma<<<dim3(1,4,256), 256, GSMEM>>>(Ps, Vt, nullptr, O,
        NTOK, 128, 1344, 896, 896, 256, 896, 448,
        2L*NTOK*896, (long)NTOK*896, 2L*128*896, 128L*896,
        (long)NTOK*256, 128L);
    // 12,13: projection
    convA_kernel<<<(M_TOK*256 + 255)/256, 256>>>(O, Os, M_TOK, 256);
    gemm_mma<<<dim3(2,394,1), 256, GSMEM>>>(Os, WpT, bp, P,
        M_TOK, 256, 768, 512, 512, 256, 512, 256, 0,0,0,0,0,0);
    // 14,15: residual + head
    lnres_kernel<<<M_TOK, 256>>>(ln2g, ln2b);
    head_kernel<<<BATCH, 256>>>(lncg, lncb, Wc, bc, out);
}